// round 1
// baseline (speedup 1.0000x reference)
#include <cuda_runtime.h>
#include <cuda_bf16.h>
#include <math.h>

// Problem constants
#define B    256
#define S    196
#define D    1024
#define P    512
#define L    8
#define TOPK 4

// k-split for sim GEMM
#define KSPLIT 8
#define KCH    (D / KSPLIT)   // 128

// Scratch (no cudaMalloc allowed)
__device__ float g_qpart[4][B * D];        // 4 MB  partial sums over S
__device__ float g_qn[B * D];              // normalized query
__device__ float g_keyn[P * D];            // normalized keys
__device__ float g_simpart[KSPLIT][B * P]; // 4 MB  partial sims
__device__ int   g_idx[TOPK * B];

// ---------------------------------------------------------------------------
// K1: partial mean over sequence dim. grid(B, 4), block 256.
// Each block sums 49 s-steps for one b; thread t owns float4 d-chunk t.
// ---------------------------------------------------------------------------
__global__ void k_mean_partial(const float* __restrict__ x) {
    int b  = blockIdx.x;
    int sc = blockIdx.y;
    int t  = threadIdx.x;
    const float4* xp = (const float4*)x + (size_t)(b * S + sc * 49) * (D / 4) + t;
    float ax = 0.f, ay = 0.f, az = 0.f, aw = 0.f;
#pragma unroll 7
    for (int s = 0; s < 49; s++) {
        float4 v = xp[(size_t)s * (D / 4)];
        ax += v.x; ay += v.y; az += v.z; aw += v.w;
    }
    float4 r = make_float4(ax, ay, az, aw);
    ((float4*)g_qpart[sc])[b * (D / 4) + t] = r;
}

// ---------------------------------------------------------------------------
// block reduce-sum helper (256 threads)
// ---------------------------------------------------------------------------
__device__ __forceinline__ float block_sum_256(float v, float* warp_smem) {
    int t = threadIdx.x;
#pragma unroll
    for (int o = 16; o > 0; o >>= 1) v += __shfl_down_sync(0xffffffffu, v, o);
    if ((t & 31) == 0) warp_smem[t >> 5] = v;
    __syncthreads();
    if (t < 8) {
        float s = warp_smem[t];
#pragma unroll
        for (int o = 4; o > 0; o >>= 1) s += __shfl_down_sync(0xffu, s, o);
        if (t == 0) warp_smem[0] = s;
    }
    __syncthreads();
    float r = warp_smem[0];
    __syncthreads();
    return r;
}

// ---------------------------------------------------------------------------
// K2: finalize query: sum 4 partials, /196, L2-normalize.  grid(B), block 256.
// ---------------------------------------------------------------------------
__global__ void k_finalize_q() {
    __shared__ float wsum[8];
    int b = blockIdx.x;
    int t = threadIdx.x;
    float4 v = make_float4(0.f, 0.f, 0.f, 0.f);
#pragma unroll
    for (int sc = 0; sc < 4; sc++) {
        float4 p = ((const float4*)g_qpart[sc])[b * (D / 4) + t];
        v.x += p.x; v.y += p.y; v.z += p.z; v.w += p.w;
    }
    const float inv = 1.0f / 196.0f;
    v.x *= inv; v.y *= inv; v.z *= inv; v.w *= inv;
    float ss = v.x * v.x + v.y * v.y + v.z * v.z + v.w * v.w;
    ss = block_sum_256(ss, wsum);
    float rs = rsqrtf(fmaxf(ss, 1e-12f));
    v.x *= rs; v.y *= rs; v.z *= rs; v.w *= rs;
    ((float4*)g_qn)[b * (D / 4) + t] = v;
}

// ---------------------------------------------------------------------------
// K3: normalize keys.  grid(P), block 256.
// ---------------------------------------------------------------------------
__global__ void k_norm_keys(const float* __restrict__ key) {
    __shared__ float wsum[8];
    int p = blockIdx.x;
    int t = threadIdx.x;
    float4 v = ((const float4*)key)[p * (D / 4) + t];
    float ss = v.x * v.x + v.y * v.y + v.z * v.z + v.w * v.w;
    ss = block_sum_256(ss, wsum);
    float rs = rsqrtf(fmaxf(ss, 1e-12f));
    v.x *= rs; v.y *= rs; v.z *= rs; v.w *= rs;
    ((float4*)g_keyn)[p * (D / 4) + t] = v;
}

// ---------------------------------------------------------------------------
// K4: sim GEMM  sim[b,p] = dot(qn[b], keyn[p]).
// 64x64 tile, 256 threads, 4x4 accumulators, k-split over grid.z.
// smem panels stored transposed [k][row] so compute reads are float4.
// grid(4, 8, KSPLIT), block 256.
// ---------------------------------------------------------------------------
__global__ void k_sim_gemm() {
    __shared__ float As[16][64];
    __shared__ float Bs[16][64];
    int t  = threadIdx.x;
    int b0 = blockIdx.x * 64;
    int p0 = blockIdx.y * 64;
    int k0 = blockIdx.z * KCH;
    int tx = t & 15;        // p sub-tile
    int ty = t >> 4;        // b sub-tile (0..15)
    int lr  = t >> 2;       // loader row 0..63
    int lk4 = t & 3;        // loader k-quad 0..3

    float acc[4][4];
#pragma unroll
    for (int i = 0; i < 4; i++)
#pragma unroll
        for (int j = 0; j < 4; j++) acc[i][j] = 0.f;

    for (int kk = 0; kk < KCH; kk += 16) {
        float4 a4 = *(const float4*)&g_qn  [(b0 + lr) * D + k0 + kk + lk4 * 4];
        float4 b4 = *(const float4*)&g_keyn[(p0 + lr) * D + k0 + kk + lk4 * 4];
        __syncthreads();
        As[lk4 * 4 + 0][lr] = a4.x; As[lk4 * 4 + 1][lr] = a4.y;
        As[lk4 * 4 + 2][lr] = a4.z; As[lk4 * 4 + 3][lr] = a4.w;
        Bs[lk4 * 4 + 0][lr] = b4.x; Bs[lk4 * 4 + 1][lr] = b4.y;
        Bs[lk4 * 4 + 2][lr] = b4.z; Bs[lk4 * 4 + 3][lr] = b4.w;
        __syncthreads();
#pragma unroll
        for (int k = 0; k < 16; k++) {
            float4 av = *(const float4*)&As[k][ty * 4];
            float4 bv = *(const float4*)&Bs[k][tx * 4];
            acc[0][0] += av.x * bv.x; acc[0][1] += av.x * bv.y;
            acc[0][2] += av.x * bv.z; acc[0][3] += av.x * bv.w;
            acc[1][0] += av.y * bv.x; acc[1][1] += av.y * bv.y;
            acc[1][2] += av.y * bv.z; acc[1][3] += av.y * bv.w;
            acc[2][0] += av.z * bv.x; acc[2][1] += av.z * bv.y;
            acc[2][2] += av.z * bv.z; acc[2][3] += av.z * bv.w;
            acc[3][0] += av.w * bv.x; acc[3][1] += av.w * bv.y;
            acc[3][2] += av.w * bv.z; acc[3][3] += av.w * bv.w;
        }
    }
    float* out = g_simpart[blockIdx.z];
#pragma unroll
    for (int i = 0; i < 4; i++)
#pragma unroll
        for (int j = 0; j < 4; j++)
            out[(b0 + ty * 4 + i) * P + (p0 + tx * 4 + j)] = acc[i][j];
}

// ---------------------------------------------------------------------------
// K5: top-k selection with gumbel noise (argmax == argmax of softmax, first
// occurrence on ties).  grid(B), block 256.
// ---------------------------------------------------------------------------
__global__ void k_select(const float* __restrict__ gu) {
    __shared__ float sval[P];
    __shared__ float rv[8];
    __shared__ int   ri[8];
    int b = blockIdx.x;
    int t = threadIdx.x;

    for (int p = t; p < P; p += 256) {
        float s = 0.f;
#pragma unroll
        for (int c = 0; c < KSPLIT; c++) s += g_simpart[c][b * P + p];
        sval[p] = s;
    }
    __syncthreads();

    for (int i = 0; i < TOPK; i++) {
        float bv = -1e30f;
        int   bi = 0;
        for (int p = t; p < P; p += 256) {
            float u = gu[((size_t)i * B + b) * P + p];
            float g = -logf(-logf(u + 1e-10f) + 1e-10f);
            float v = sval[p] + g;
            if (v > bv) { bv = v; bi = p; }   // strict > keeps first occurrence
        }
#pragma unroll
        for (int o = 16; o > 0; o >>= 1) {
            float ov = __shfl_down_sync(0xffffffffu, bv, o);
            int   oi = __shfl_down_sync(0xffffffffu, bi, o);
            if (ov > bv || (ov == bv && oi < bi)) { bv = ov; bi = oi; }
        }
        if ((t & 31) == 0) { rv[t >> 5] = bv; ri[t >> 5] = bi; }
        __syncthreads();
        if (t == 0) {
            float fv = rv[0]; int fi = ri[0];
#pragma unroll
            for (int w = 1; w < 8; w++) {
                if (rv[w] > fv || (rv[w] == fv && ri[w] < fi)) { fv = rv[w]; fi = ri[w]; }
            }
            g_idx[i * B + b] = fi;
            sval[fi] -= 1000.0f;   // straight-through mask-out (w==hard numerically)
        }
        __syncthreads();
    }
}

// ---------------------------------------------------------------------------
// K6: gather prompt rows to output.  grid(B*TOPK), block 256.
// out[b, i*8+l, d] = prompt[idx[i][b], l, d]
// ---------------------------------------------------------------------------
__global__ void k_gather(const float* __restrict__ prompt, float* __restrict__ out) {
    int bid = blockIdx.x;
    int b = bid >> 2;
    int i = bid & 3;
    int idx = g_idx[i * B + b];
    const float4* src = (const float4*)prompt + (size_t)idx * (L * D / 4);
    float4*       dst = (float4*)out + (size_t)b * (TOPK * L * D / 4) + i * (L * D / 4);
    int t = threadIdx.x;
#pragma unroll
    for (int j = 0; j < (L * D / 4) / 256; j++)
        dst[t + j * 256] = src[t + j * 256];
}

// ---------------------------------------------------------------------------
extern "C" void kernel_launch(void* const* d_in, const int* in_sizes, int n_in,
                              void* d_out, int out_size) {
    const float* x_embed    = (const float*)d_in[0];
    const float* prompt     = (const float*)d_in[1];
    const float* prompt_key = (const float*)d_in[2];
    const float* gumbel_u   = (const float*)d_in[3];
    float* out = (float*)d_out;

    k_mean_partial<<<dim3(B, 4), 256>>>(x_embed);
    k_finalize_q  <<<B, 256>>>();
    k_norm_keys   <<<P, 256>>>(prompt_key);
    k_sim_gemm    <<<dim3(B / 64, P / 64, KSPLIT), 256>>>();
    k_select      <<<B, 256>>>(gumbel_u);
    k_gather      <<<B * TOPK, 256>>>(prompt, out);
}

// round 2
// speedup vs baseline: 1.0234x; 1.0234x over previous
#include <cuda_runtime.h>
#include <cuda_bf16.h>
#include <math.h>

// Problem constants
#define B    256
#define S    196
#define D    1024
#define P    512
#define L    8
#define TOPK 4

// k-split for sim GEMM
#define KSPLIT 16
#define KCH    (D / KSPLIT)   // 64

// Scratch (no cudaMalloc allowed)
__device__ float g_qpart[4][B * D];        // partial sums over S
__device__ float g_qn[B * D];              // normalized query
__device__ float g_keyn[P * D];            // normalized keys
__device__ float g_simpart[KSPLIT][B * P]; // partial sims

// ---------------------------------------------------------------------------
// f32x2 packed-FMA helpers (FFMA2 — two independent IEEE fp32 FMAs per instr)
// ---------------------------------------------------------------------------
__device__ __forceinline__ unsigned long long fma2(unsigned long long a,
                                                   unsigned long long b,
                                                   unsigned long long c) {
    unsigned long long d;
    asm("fma.rn.f32x2 %0, %1, %2, %3;" : "=l"(d) : "l"(a), "l"(b), "l"(c));
    return d;
}
__device__ __forceinline__ unsigned long long pack2(float x, float y) {
    unsigned long long d;
    asm("mov.b64 %0, {%1, %2};" : "=l"(d) : "f"(x), "f"(y));
    return d;
}
__device__ __forceinline__ void unpack2(unsigned long long v, float& x, float& y) {
    asm("mov.b64 {%0, %1}, %2;" : "=f"(x), "=f"(y) : "l"(v));
}

// ---------------------------------------------------------------------------
// K1: partial mean over sequence dim. grid(B, 4), block 256.
// ---------------------------------------------------------------------------
__global__ void k_mean_partial(const float* __restrict__ x) {
    int b  = blockIdx.x;
    int sc = blockIdx.y;
    int t  = threadIdx.x;
    const float4* xp = (const float4*)x + (size_t)(b * S + sc * 49) * (D / 4) + t;
    float ax = 0.f, ay = 0.f, az = 0.f, aw = 0.f;
#pragma unroll 7
    for (int s = 0; s < 49; s++) {
        float4 v = xp[(size_t)s * (D / 4)];
        ax += v.x; ay += v.y; az += v.z; aw += v.w;
    }
    ((float4*)g_qpart[sc])[b * (D / 4) + t] = make_float4(ax, ay, az, aw);
}

// ---------------------------------------------------------------------------
// block reduce-sum helper (256 threads)
// ---------------------------------------------------------------------------
__device__ __forceinline__ float block_sum_256(float v, float* warp_smem) {
    int t = threadIdx.x;
#pragma unroll
    for (int o = 16; o > 0; o >>= 1) v += __shfl_down_sync(0xffffffffu, v, o);
    if ((t & 31) == 0) warp_smem[t >> 5] = v;
    __syncthreads();
    if (t < 8) {
        float s = warp_smem[t];
#pragma unroll
        for (int o = 4; o > 0; o >>= 1) s += __shfl_down_sync(0xffu, s, o);
        if (t == 0) warp_smem[0] = s;
    }
    __syncthreads();
    float r = warp_smem[0];
    __syncthreads();
    return r;
}

// ---------------------------------------------------------------------------
// K2: finalize query: sum 4 partials, /196, L2-normalize.  grid(B), block 256.
// ---------------------------------------------------------------------------
__global__ void k_finalize_q() {
    __shared__ float wsum[8];
    int b = blockIdx.x;
    int t = threadIdx.x;
    float4 v = make_float4(0.f, 0.f, 0.f, 0.f);
#pragma unroll
    for (int sc = 0; sc < 4; sc++) {
        float4 p = ((const float4*)g_qpart[sc])[b * (D / 4) + t];
        v.x += p.x; v.y += p.y; v.z += p.z; v.w += p.w;
    }
    const float inv = 1.0f / 196.0f;
    v.x *= inv; v.y *= inv; v.z *= inv; v.w *= inv;
    float ss = v.x * v.x + v.y * v.y + v.z * v.z + v.w * v.w;
    ss = block_sum_256(ss, wsum);
    float rs = rsqrtf(fmaxf(ss, 1e-12f));
    v.x *= rs; v.y *= rs; v.z *= rs; v.w *= rs;
    ((float4*)g_qn)[b * (D / 4) + t] = v;
}

// ---------------------------------------------------------------------------
// K3: normalize keys.  grid(P), block 256.
// ---------------------------------------------------------------------------
__global__ void k_norm_keys(const float* __restrict__ key) {
    __shared__ float wsum[8];
    int p = blockIdx.x;
    int t = threadIdx.x;
    float4 v = ((const float4*)key)[p * (D / 4) + t];
    float ss = v.x * v.x + v.y * v.y + v.z * v.z + v.w * v.w;
    ss = block_sum_256(ss, wsum);
    float rs = rsqrtf(fmaxf(ss, 1e-12f));
    v.x *= rs; v.y *= rs; v.z *= rs; v.w *= rs;
    ((float4*)g_keyn)[p * (D / 4) + t] = v;
}

// ---------------------------------------------------------------------------
// K4: sim GEMM  sim[b,p] = dot(qn[b], keyn[p]).
// 64x64 tile, 256 threads, 4x4 accumulators held as f32x2 pairs.
// Entire 64-k chunk staged in smem: ONE sync, then 64 k-steps uninterrupted.
// grid(4, 8, KSPLIT), block 256.
// ---------------------------------------------------------------------------
__global__ void __launch_bounds__(256) k_sim_gemm() {
    __shared__ float As[KCH][64];   // [k][row]
    __shared__ float Bs[KCH][64];
    int t  = threadIdx.x;
    int b0 = blockIdx.x * 64;
    int p0 = blockIdx.y * 64;
    int k0 = blockIdx.z * KCH;
    int tx = t & 15;        // p sub-tile
    int ty = t >> 4;        // b sub-tile
    int lr = t & 63;        // loader row
    int ks = t >> 6;        // loader k-slab (0..3)

    // load phase: each thread loads 4 float4 from A and 4 from B
#pragma unroll
    for (int c4 = 0; c4 < 4; c4++) {
        int k4 = ks * 4 + c4;                       // float4 group 0..15
        float4 a4 = *(const float4*)&g_qn  [(b0 + lr) * D + k0 + k4 * 4];
        float4 b4 = *(const float4*)&g_keyn[(p0 + lr) * D + k0 + k4 * 4];
        As[k4 * 4 + 0][lr] = a4.x; As[k4 * 4 + 1][lr] = a4.y;
        As[k4 * 4 + 2][lr] = a4.z; As[k4 * 4 + 3][lr] = a4.w;
        Bs[k4 * 4 + 0][lr] = b4.x; Bs[k4 * 4 + 1][lr] = b4.y;
        Bs[k4 * 4 + 2][lr] = b4.z; Bs[k4 * 4 + 3][lr] = b4.w;
    }
    __syncthreads();

    unsigned long long acc[4][2];
#pragma unroll
    for (int i = 0; i < 4; i++) { acc[i][0] = 0ull; acc[i][1] = 0ull; }

#pragma unroll 8
    for (int k = 0; k < KCH; k++) {
        float4 av = *(const float4*)&As[k][ty * 4];
        float4 bv = *(const float4*)&Bs[k][tx * 4];
        unsigned long long b01 = pack2(bv.x, bv.y);
        unsigned long long b23 = pack2(bv.z, bv.w);
        unsigned long long a0 = pack2(av.x, av.x);
        unsigned long long a1 = pack2(av.y, av.y);
        unsigned long long a2 = pack2(av.z, av.z);
        unsigned long long a3 = pack2(av.w, av.w);
        acc[0][0] = fma2(a0, b01, acc[0][0]); acc[0][1] = fma2(a0, b23, acc[0][1]);
        acc[1][0] = fma2(a1, b01, acc[1][0]); acc[1][1] = fma2(a1, b23, acc[1][1]);
        acc[2][0] = fma2(a2, b01, acc[2][0]); acc[2][1] = fma2(a2, b23, acc[2][1]);
        acc[3][0] = fma2(a3, b01, acc[3][0]); acc[3][1] = fma2(a3, b23, acc[3][1]);
    }

    float* out = g_simpart[blockIdx.z];
#pragma unroll
    for (int i = 0; i < 4; i++) {
        float4 r;
        unpack2(acc[i][0], r.x, r.y);
        unpack2(acc[i][1], r.z, r.w);
        *(float4*)&out[(b0 + ty * 4 + i) * P + p0 + tx * 4] = r;
    }
}

// ---------------------------------------------------------------------------
// K5: fused top-k selection (gumbel argmax, straight-through == gather) +
// output gather.  grid(B), block 256.
// ---------------------------------------------------------------------------
__global__ void k_select_gather(const float* __restrict__ gu,
                                const float* __restrict__ prompt,
                                float* __restrict__ out) {
    __shared__ float sval[P];
    __shared__ float rv[8];
    __shared__ int   ri[8];
    __shared__ int   sidx;
    int b = blockIdx.x;
    int t = threadIdx.x;

    for (int p = t; p < P; p += 256) {
        float s = 0.f;
#pragma unroll
        for (int c = 0; c < KSPLIT; c++) s += g_simpart[c][b * P + p];
        sval[p] = s;
    }
    __syncthreads();

    for (int i = 0; i < TOPK; i++) {
        float bv = -1e30f;
        int   bi = 0;
        for (int p = t; p < P; p += 256) {
            float u = gu[((size_t)i * B + b) * P + p];
            float g = -logf(-logf(u + 1e-10f) + 1e-10f);
            float v = sval[p] + g;
            if (v > bv) { bv = v; bi = p; }   // strict > keeps first occurrence
        }
#pragma unroll
        for (int o = 16; o > 0; o >>= 1) {
            float ov = __shfl_down_sync(0xffffffffu, bv, o);
            int   oi = __shfl_down_sync(0xffffffffu, bi, o);
            if (ov > bv || (ov == bv && oi < bi)) { bv = ov; bi = oi; }
        }
        if ((t & 31) == 0) { rv[t >> 5] = bv; ri[t >> 5] = bi; }
        __syncthreads();
        if (t == 0) {
            float fv = rv[0]; int fi = ri[0];
#pragma unroll
            for (int w = 1; w < 8; w++) {
                if (rv[w] > fv || (rv[w] == fv && ri[w] < fi)) { fv = rv[w]; fi = ri[w]; }
            }
            sidx = fi;
            sval[fi] -= 1000.0f;   // training-mode mask-out (w == hard numerically)
        }
        __syncthreads();
        int idx = sidx;
        // gather: out[b, i*L:(i+1)*L, :] = prompt[idx]
        const float4* src = (const float4*)prompt + (size_t)idx * (L * D / 4);
        float4*       dst = (float4*)out + (size_t)b * (TOPK * L * D / 4) + i * (L * D / 4);
#pragma unroll
        for (int j = 0; j < (L * D / 4) / 256; j++)
            dst[t + j * 256] = src[t + j * 256];
        __syncthreads();
    }
}

// ---------------------------------------------------------------------------
extern "C" void kernel_launch(void* const* d_in, const int* in_sizes, int n_in,
                              void* d_out, int out_size) {
    const float* x_embed    = (const float*)d_in[0];
    const float* prompt     = (const float*)d_in[1];
    const float* prompt_key = (const float*)d_in[2];
    const float* gumbel_u   = (const float*)d_in[3];
    float* out = (float*)d_out;

    k_mean_partial <<<dim3(B, 4), 256>>>(x_embed);
    k_finalize_q   <<<B, 256>>>();
    k_norm_keys    <<<P, 256>>>(prompt_key);
    k_sim_gemm     <<<dim3(B / 64, P / 64, KSPLIT), 256>>>();
    k_select_gather<<<B, 256>>>(gumbel_u, prompt, out);
}